// round 11
// baseline (speedup 1.0000x reference)
#include <cuda_runtime.h>
#include <cuda_bf16.h>
#include <cstddef>

// Soft-Viterbi DP (N=M=2048, 3 states) in LINEAR space with per-lane
// power-of-2 scaling: state E = exp(V - K*ln2). lse3 -> FFMA dot products.
// Boundary V=-1e8 -> exactly 0 (validated rel_err 3.3e-6).
//
// G=16 CTAs x 32 lanes x C=4 columns/lane, barrier-free warp-shuffle
// systolic array. Cross-CTA boundary protocol rebuilt for true overlap:
//   - LAG=32 rows of slack established in the consumer prologue, so the
//     steady-state consumer never blocks and polls only when its cached
//     progress value runs out (~1 poll / 27 steps).
//   - each progress counter padded to its own 128B line (no LTS
//     same-address serialization between spinners and producers).
//   - spin loops back off with __nanosleep.

#define NN 2048
#define MM 2048
#define G  16
#define T  32
#define C  4
#define W  (T * C)            // 128 columns per CTA
#define STEPS (NN + T - 1)
#define LAG 32                // boundary slack (rows)
#define QD  5                 // consumer register queue depth (h1 + q0..q3)

static_assert(G * W == MM, "column coverage");

__device__ float4 g_edge[G - 1][NN + 1];  // (em,ex,ey,K-bits) of col (g+1)*W
struct alignas(128) PadCtr { int v; int pad[31]; };
__device__ PadCtr g_prog[G - 1];          // one 128B line per counter

__device__ __forceinline__ int ld_acq(const int* p) {
    int v;
    asm volatile("ld.global.acquire.gpu.b32 %0, [%1];" : "=r"(v) : "l"(p) : "memory");
    return v;
}
__device__ __forceinline__ void st_rel(int* p, int v) {
    asm volatile("st.global.release.gpu.b32 [%0], %1;" :: "l"(p), "r"(v) : "memory");
}
__device__ __forceinline__ float exp2i(int n) {  // 2^n, clamped to normals
    n = max(-126, min(127, n));
    return __int_as_float((n + 127) << 23);
}

__global__ void viterbi_init_kernel() {
    if (threadIdx.x < G - 1) g_prog[threadIdx.x].v = 0;
}

__global__ __launch_bounds__(T, 1)
void ViterbiDecoder_5506148073875_kernel(const float* __restrict__ theta,
                                         const float* __restrict__ A,
                                         float* __restrict__ out) {
    const int g  = blockIdx.x;
    const int l  = threadIdx.x;
    const int jb = g * W + l * C;  // 0-based first theta column of this lane

    const float ea00 = __expf(A[0]), ea01 = __expf(A[1]), ea02 = __expf(A[2]);
    const float ea10 = __expf(A[3]), ea11 = __expf(A[4]), ea12 = __expf(A[5]);
    const float ea20 = __expf(A[6]), ea21 = __expf(A[7]), ea22 = __expf(A[8]);

    // Previous-row state for 4 cells: p[c*3 + {m,x,y}], common scale K.
    float p[12];
#pragma unroll
    for (int k = 0; k < 12; ++k) p[k] = 0.f;   // row 0: V=-inf -> 0
    int K = 0;

    // Neighbor (col jb, 1-based) history: h1 = row i (left), h2 = row i-1 (diag).
    float h1m = 0.f, h1x = 0.f, h1y = 0.f; int h1k = 0;
    float h2m = 0.f, h2x = 0.f, h2y = 0.f; int h2k = 0;
    if (g == 0 && l == 0) h2m = 1.f;  // V[0,0] = [0,-inf,-inf] -> (1,0,0)

    // ---- theta pipeline: th_e = exp(theta row i); u = row i+1; v = row i+2.
    const float4* tbase = reinterpret_cast<const float4*>(theta);
    auto trow = [&](int r) {  // r = 1-based row; 12 floats = 3 float4
        return tbase + ((size_t)(r - 1) * MM + jb) * 3 / 4;
    };
    float th_e[12];
    float4 u0, u1, u2, v0, v1, v2;
    {
        const float4* r1 = trow(1); float4 w0 = r1[0], w1 = r1[1], w2 = r1[2];
        const float4* r2 = trow(2); u0 = r2[0]; u1 = r2[1]; u2 = r2[2];
        const float4* r3 = trow(3); v0 = r3[0]; v1 = r3[1]; v2 = r3[2];
        th_e[0] = __expf(w0.x); th_e[1] = __expf(w0.y); th_e[2]  = __expf(w0.z);
        th_e[3] = __expf(w0.w); th_e[4] = __expf(w1.x); th_e[5]  = __expf(w1.y);
        th_e[6] = __expf(w1.z); th_e[7] = __expf(w1.w); th_e[8]  = __expf(w2.x);
        th_e[9] = __expf(w2.y); th_e[10] = __expf(w2.z); th_e[11] = __expf(w2.w);
    }

    // ---- cross-CTA edge pipeline (consumer: lane 0 of g > 0).
    const int* pp = (g > 0) ? &g_prog[g - 1].v : nullptr;
    int known = 0;
    float4 q0 = {0,0,0,0}, q1 = {0,0,0,0}, q2 = {0,0,0,0}, q3 = {0,0,0,0};
    if (g > 0 && l == 0) {
        // Establish LAG rows of slack before starting.
        while ((known = ld_acq(pp)) < QD + LAG) __nanosleep(128);
        float4 e = g_edge[g - 1][1];
        h1m = e.x; h1x = e.y; h1y = e.z; h1k = __float_as_int(e.w);
        q0 = g_edge[g - 1][2]; q1 = g_edge[g - 1][3];
        q2 = g_edge[g - 1][4]; q3 = g_edge[g - 1][5];
    }

    for (int s = 0; s < STEPS; ++s) {
        const int i = s - l + 1;  // 1-based row this lane computes

        // Issue theta load for row i+3 (consumed ~2.2 steps later).
        float4 t0, t1, t2;
        const int rth = i + 3;
        const bool ldth = (rth >= 4 && rth <= NN);
        if (ldth) { const float4* tp = trow(rth); t0 = tp[0]; t1 = tp[1]; t2 = tp[2]; }

        if (i >= 1 && i <= NN) {
            // Align all operands to the largest scale.
            const int kref = max(K, max(h1k, h2k));
            const float fo = exp2i(K   - kref);
            const float fl = exp2i(h1k - kref);
            const float fd = exp2i(h2k - kref);

            float sp[12];
#pragma unroll
            for (int k = 0; k < 12; ++k) sp[k] = p[k] * fo;

            const float dm = h2m * fd, dx = h2x * fd, dy = h2y * fd;
            const float lm = h1m * fl, lx = h1x * fl, ly = h1y * fl;

            float n[12];
#pragma unroll
            for (int c = 0; c < 4; ++c) {
                const float cdm = (c == 0) ? dm : sp[3*c - 3];
                const float cdx = (c == 0) ? dx : sp[3*c - 2];
                const float cdy = (c == 0) ? dy : sp[3*c - 1];
                const float clm = (c == 0) ? lm : n[3*c - 3];
                const float clx = (c == 0) ? lx : n[3*c - 2];
                const float cly = (c == 0) ? ly : n[3*c - 1];
                n[3*c + 0] = th_e[3*c + 0] *
                    fmaf(cdm, ea00, fmaf(cdx, ea01, cdy * ea02));
                n[3*c + 1] = th_e[3*c + 1] *
                    fmaf(sp[3*c], ea10, fmaf(sp[3*c+1], ea11, sp[3*c+2] * ea12));
                n[3*c + 2] = th_e[3*c + 2] *
                    fmaf(clm, ea20, fmaf(clx, ea21, cly * ea22));
            }

            // Renormalize row so max lands in [1,2); bump scale K.
            float mx = n[0];
#pragma unroll
            for (int k = 1; k < 12; ++k) mx = fmaxf(mx, n[k]);
            const int   sh = ((__float_as_int(mx) >> 23) & 0xff) - 127;
            const float fn = exp2i(-sh);
#pragma unroll
            for (int k = 0; k < 12; ++k) p[k] = n[k] * fn;
            K = kref + sh;

            if (l == T - 1 && g < G - 1) {  // producer: publish last cell
                g_edge[g][i] = make_float4(p[9], p[10], p[11], __int_as_float(K));
                if ((i & 1) == 0 || i == NN) st_rel(&g_prog[g].v, i);
            }
            if (g == G - 1 && l == T - 1 && i == NN)
                out[0] = (float)K * 0.69314718055994531f +
                         __logf(p[9] + p[10] + p[11]);
        }

        // Pass edge (last cell, renormed) to lane l+1; rotate history.
        const float rm = __shfl_up_sync(0xffffffffu, p[9],  1);
        const float rx = __shfl_up_sync(0xffffffffu, p[10], 1);
        const float ry = __shfl_up_sync(0xffffffffu, p[11], 1);
        const int   rk = __shfl_up_sync(0xffffffffu, K, 1);

        h2m = h1m; h2x = h1x; h2y = h1y; h2k = h1k;
        if (l == 0) {
            if (g > 0) {
                h1m = q0.x; h1x = q0.y; h1y = q0.z; h1k = __float_as_int(q0.w);
                q0 = q1; q1 = q2; q2 = q3;
                const int f = i + QD;  // refill queue tail
                if (f <= NN) {
                    if (known < f) {  // rare: ~1 per (LAG-QD) steps
                        while ((known = ld_acq(pp)) < f) __nanosleep(64);
                    }
                    q3 = g_edge[g - 1][f];
                } else {
                    q3 = make_float4(0.f, 0.f, 0.f, 0.f);
                }
            } else {
                h1m = 0.f; h1x = 0.f; h1y = 0.f; h1k = 0;  // V[i,0] = -inf
            }
        } else {
            h1m = rm; h1x = rx; h1y = ry; h1k = rk;
        }

        // Rotate theta pipeline for next row (row 1 came from prologue).
        const int inext = i + 1;
        if (inext >= 2 && inext <= NN) {
            th_e[0] = __expf(u0.x); th_e[1] = __expf(u0.y); th_e[2]  = __expf(u0.z);
            th_e[3] = __expf(u0.w); th_e[4] = __expf(u1.x); th_e[5]  = __expf(u1.y);
            th_e[6] = __expf(u1.z); th_e[7] = __expf(u1.w); th_e[8]  = __expf(u2.x);
            th_e[9] = __expf(u2.y); th_e[10] = __expf(u2.z); th_e[11] = __expf(u2.w);
            u0 = v0; u1 = v1; u2 = v2;
            v0 = t0; v1 = t1; v2 = t2;
        }
    }
}

extern "C" void kernel_launch(void* const* d_in, const int* in_sizes, int n_in,
                              void* d_out, int out_size) {
    const float* theta = (const float*)d_in[0];
    const float* A     = (const float*)d_in[1];
    if (n_in >= 2 && in_sizes[0] == 9) {  // defensive: swap if order differs
        theta = (const float*)d_in[1];
        A     = (const float*)d_in[0];
    }
    viterbi_init_kernel<<<1, G>>>();  // reset cross-CTA progress (per replay)
    ViterbiDecoder_5506148073875_kernel<<<G, T>>>(theta, A, (float*)d_out);
}

// round 12
// speedup vs baseline: 1.0427x; 1.0427x over previous
#include <cuda_runtime.h>
#include <cuda_bf16.h>
#include <cstddef>

// Soft-Viterbi DP (N=M=2048, 3 states) in LINEAR space with per-lane
// power-of-2 scaling: state E = exp(V - K*ln2); lse3 -> FFMA dot products.
// Boundary V=-1e8 -> exactly 0. Output: K*ln2 + log(em+ex+ey).
//
// R12 structure:
//  - eth_kernel: whole-chip precompute of exp(theta) into a __device__
//    scratch array -> zero MUFU in the DP hot loop.
//  - DP kernel: G=16 CTAs x 64 threads. Warp 0 = compute (32 lanes x 4
//    columns, skewed systolic, shfl edge passing). Warp 1 = edge
//    prefetcher: polls the upstream progress counter, batch-copies edge
//    rows into a 64-row SMEM ring, bumps a volatile head counter. The
//    compute warp reads edges from SMEM and (in steady state) never
//    touches L2 for synchronization -> all CTAs' compute warps run the
//    identical instruction stream -> pipeline slack persists.

#define NN 2048
#define MM 2048
#define G  16
#define T  32
#define C  4
#define W  (T * C)            // 128 columns per CTA
#define STEPS (NN + T - 1)
#define RB  64                // SMEM ring rows (power of 2)
#define RBM (RB - 1)
#define BATCH 8               // prefetch batch (rows)

static_assert(G * W == MM, "column coverage");

__device__ float  g_eth[(size_t)NN * MM * 3];     // exp(theta), 50.3 MB scratch
__device__ float4 g_edge[G - 1][NN + 1];          // (em,ex,ey,K-bits) per boundary
struct alignas(128) PadCtr { int v; int pad[31]; };
__device__ PadCtr g_prog[G - 1];

__device__ __forceinline__ int ld_acq(const int* p) {
    int v;
    asm volatile("ld.global.acquire.gpu.b32 %0, [%1];" : "=r"(v) : "l"(p) : "memory");
    return v;
}
__device__ __forceinline__ void st_rel(int* p, int v) {
    asm volatile("st.global.release.gpu.b32 [%0], %1;" :: "l"(p), "r"(v) : "memory");
}
__device__ __forceinline__ float exp2i(int n) {  // 2^n, clamped to normals
    n = max(-126, min(127, n));
    return __int_as_float((n + 127) << 23);
}

__global__ void viterbi_init_kernel() {
    if (threadIdx.x < G - 1) g_prog[threadIdx.x].v = 0;
}

// Whole-chip exp(theta) precompute: MUFU-parallel, ~8us.
__global__ void eth_kernel(const float* __restrict__ theta) {
    const float4* in  = reinterpret_cast<const float4*>(theta);
    float4*       o   = reinterpret_cast<float4*>(g_eth);
    const size_t  n4  = (size_t)NN * MM * 3 / 4;
    for (size_t k = (size_t)blockIdx.x * blockDim.x + threadIdx.x; k < n4;
         k += (size_t)gridDim.x * blockDim.x) {
        float4 v = in[k];
        o[k] = make_float4(__expf(v.x), __expf(v.y), __expf(v.z), __expf(v.w));
    }
}

__global__ __launch_bounds__(64, 1)
void ViterbiDecoder_5506148073875_kernel(const float* __restrict__ A,
                                         float* __restrict__ out) {
    __shared__ float4 s_ring[RB];
    __shared__ int    s_head;   // highest edge row available in ring
    __shared__ int    s_cons;   // highest edge row fully consumed

    const int g   = blockIdx.x;
    const int tid = threadIdx.x;
    const int wrp = tid >> 5;
    const int l   = tid & 31;

    // ---- SMEM init (both warps), one and only block barrier.
    if (tid < RB) s_ring[tid] = make_float4(0.f, 0.f, 0.f, 0.f);
    if (tid == 0) {
        s_head = (g == 0) ? (NN + 2) : 0;  // g==0: ring of zeros, always ready
        s_cons = 0;
    }
    __syncthreads();

    // ================= Warp 1: edge prefetcher =================
    if (wrp == 1) {
        if (g == 0) return;  // nothing to fetch; ring stays zero
        const int* pp = &g_prog[g - 1].v;
        int done = 0;
        while (done < NN) {
            const int r_end = min(done + BATCH, NN);
            // every lane acquires (orders its own subsequent loads)
            int known;
            while ((known = ld_acq(pp)) < r_end) __nanosleep(64);
            // ring space: rows (done+1 .. r_end) overwrite rows - RB
            while (r_end - *(volatile int*)&s_cons > RB) __nanosleep(64);
            const int r = done + 1 + l;
            if (r <= r_end) s_ring[r & RBM] = g_edge[g - 1][r];
            __syncwarp();
            __threadfence_block();
            if (l == 0) *(volatile int*)&s_head = r_end;
            __syncwarp();
            done = r_end;
        }
        return;
    }

    // ================= Warp 0: compute =================
    const int jb = g * W + l * C;  // 0-based first column of this lane

    const float ea00 = __expf(A[0]), ea01 = __expf(A[1]), ea02 = __expf(A[2]);
    const float ea10 = __expf(A[3]), ea11 = __expf(A[4]), ea12 = __expf(A[5]);
    const float ea20 = __expf(A[6]), ea21 = __expf(A[7]), ea22 = __expf(A[8]);

    float p[12];
#pragma unroll
    for (int k = 0; k < 12; ++k) p[k] = 0.f;   // row 0: V=-inf -> 0
    int K = 0;

    // Neighbor column (g*W, 1-based) history: h1 = row i (left), h2 = row i-1.
    float h1m = 0.f, h1x = 0.f, h1y = 0.f; int h1k = 0;
    float h2m = 0.f, h2x = 0.f, h2y = 0.f; int h2k = 0;
    if (g == 0 && l == 0) h2m = 1.f;  // V[0,0] = [0,-inf,-inf] -> (1,0,0)

    // exp(theta) pipeline: th = row i (values), u = row i+1, v = row i+2.
    const float4* tb = reinterpret_cast<const float4*>(g_eth);
    auto trow = [&](int r) { return tb + ((size_t)(r - 1) * MM + jb) * 3 / 4; };
    float th[12];
    float4 u0, u1, u2, v0, v1, v2;
    {
        const float4* r1 = trow(1); float4 w0 = r1[0], w1 = r1[1], w2 = r1[2];
        const float4* r2 = trow(2); u0 = r2[0]; u1 = r2[1]; u2 = r2[2];
        const float4* r3 = trow(3); v0 = r3[0]; v1 = r3[1]; v2 = r3[2];
        th[0] = w0.x; th[1] = w0.y; th[2]  = w0.z; th[3]  = w0.w;
        th[4] = w1.x; th[5] = w1.y; th[6]  = w1.z; th[7]  = w1.w;
        th[8] = w2.x; th[9] = w2.y; th[10] = w2.z; th[11] = w2.w;
    }

    // Lane 0: fetch edge row 1 from the ring (g==0: head preset, zeros).
    int cached_head = (g == 0) ? (NN + 2) : 0;
    if (l == 0) {
        while (cached_head < 1) cached_head = *(volatile int*)&s_head;
        float4 e = s_ring[1 & RBM];
        h1m = e.x; h1x = e.y; h1y = e.z; h1k = __float_as_int(e.w);
    }

    for (int s = 0; s < STEPS; ++s) {
        const int i = s - l + 1;  // 1-based row this lane computes

        // Issue eth load for row i+3 (consumed ~2.2 steps later).
        float4 t0, t1, t2;
        const int rth = i + 3;
        if (rth >= 4 && rth <= NN) {
            const float4* tp = trow(rth); t0 = tp[0]; t1 = tp[1]; t2 = tp[2];
        }

        if (i >= 1 && i <= NN) {
            const int kref = max(K, max(h1k, h2k));
            const float fo = exp2i(K   - kref);
            const float fl = exp2i(h1k - kref);
            const float fd = exp2i(h2k - kref);

            float sp[12];
#pragma unroll
            for (int k = 0; k < 12; ++k) sp[k] = p[k] * fo;

            const float dm = h2m * fd, dx = h2x * fd, dy = h2y * fd;
            const float lm = h1m * fl, lx = h1x * fl, ly = h1y * fl;

            float n[12];
#pragma unroll
            for (int c = 0; c < 4; ++c) {
                const float cdm = (c == 0) ? dm : sp[3*c - 3];
                const float cdx = (c == 0) ? dx : sp[3*c - 2];
                const float cdy = (c == 0) ? dy : sp[3*c - 1];
                const float clm = (c == 0) ? lm : n[3*c - 3];
                const float clx = (c == 0) ? lx : n[3*c - 2];
                const float cly = (c == 0) ? ly : n[3*c - 1];
                n[3*c + 0] = th[3*c + 0] *
                    fmaf(cdm, ea00, fmaf(cdx, ea01, cdy * ea02));
                n[3*c + 1] = th[3*c + 1] *
                    fmaf(sp[3*c], ea10, fmaf(sp[3*c+1], ea11, sp[3*c+2] * ea12));
                n[3*c + 2] = th[3*c + 2] *
                    fmaf(clm, ea20, fmaf(clx, ea21, cly * ea22));
            }

            // Renormalize row so max lands in [1,2); bump scale K.
            float mx = n[0];
#pragma unroll
            for (int k = 1; k < 12; ++k) mx = fmaxf(mx, n[k]);
            const int   sh = ((__float_as_int(mx) >> 23) & 0xff) - 127;
            const float fn = exp2i(-sh);
#pragma unroll
            for (int k = 0; k < 12; ++k) p[k] = n[k] * fn;
            K = kref + sh;

            if (l == 0 && (i & 7) == 0) *(volatile int*)&s_cons = i;

            if (l == T - 1 && g < G - 1) {  // producer: publish row i
                g_edge[g][i] = make_float4(p[9], p[10], p[11], __int_as_float(K));
                st_rel(&g_prog[g].v, i);
            }
            if (g == G - 1 && l == T - 1 && i == NN)
                out[0] = (float)K * 0.69314718055994531f +
                         __logf(p[9] + p[10] + p[11]);
        }

        // Pass edge (last cell, renormed) to lane l+1; rotate history.
        const float rm = __shfl_up_sync(0xffffffffu, p[9],  1);
        const float rx = __shfl_up_sync(0xffffffffu, p[10], 1);
        const float ry = __shfl_up_sync(0xffffffffu, p[11], 1);
        const int   rk = __shfl_up_sync(0xffffffffu, K, 1);

        h2m = h1m; h2x = h1x; h2y = h1y; h2k = h1k;
        if (l == 0) {
            const int inext = i + 1;
            if (inext <= NN) {
                if (cached_head < inext) {
                    do { cached_head = *(volatile int*)&s_head; }
                    while (cached_head < inext);
                }
                float4 e = s_ring[inext & RBM];
                h1m = e.x; h1x = e.y; h1y = e.z; h1k = __float_as_int(e.w);
            } else {
                h1m = 0.f; h1x = 0.f; h1y = 0.f; h1k = 0;
            }
        } else {
            h1m = rm; h1x = rx; h1y = ry; h1k = rk;
        }

        // Rotate eth pipeline for next row.
        const int inext = i + 1;
        if (inext >= 2 && inext <= NN) {
            th[0] = u0.x; th[1] = u0.y; th[2]  = u0.z; th[3]  = u0.w;
            th[4] = u1.x; th[5] = u1.y; th[6]  = u1.z; th[7]  = u1.w;
            th[8] = u2.x; th[9] = u2.y; th[10] = u2.z; th[11] = u2.w;
            u0 = v0; u1 = v1; u2 = v2;
            v0 = t0; v1 = t1; v2 = t2;
        }
    }
}

extern "C" void kernel_launch(void* const* d_in, const int* in_sizes, int n_in,
                              void* d_out, int out_size) {
    const float* theta = (const float*)d_in[0];
    const float* A     = (const float*)d_in[1];
    if (n_in >= 2 && in_sizes[0] == 9) {  // defensive: swap if order differs
        theta = (const float*)d_in[1];
        A     = (const float*)d_in[0];
    }
    viterbi_init_kernel<<<1, G>>>();
    eth_kernel<<<1184, 256>>>(theta);  // whole-chip exp(theta) precompute
    ViterbiDecoder_5506148073875_kernel<<<G, 64>>>(A, (float*)d_out);
}

// round 13
// speedup vs baseline: 2.1528x; 2.0647x over previous
#include <cuda_runtime.h>
#include <cuda_bf16.h>
#include <cstddef>

// Soft-Viterbi DP (N=M=2048, 3 states m,x,y) in LINEAR space with per-thread
// power-of-2 scaling: state E = exp(V - K*ln2); lse3 -> FFMA dot products.
// Boundary V=-1e8 -> exactly 0. Output: K*ln2 + log(em+ex+ey).
// (Linear-space math validated in R9-R12: rel_err 3.3e-6.)
//
// R13 structure (single-SM, issue-bound, deterministic):
//  - eth_kernel (whole chip, ~20us): exp(theta) precomputed into 3 float4
//    planes laid out by (row, thread) so each DP theta load instruction is
//    4-line coalesced: g_eth[q][i*512 + t] = exp(theta[i, 4t .. 4t+3])[q].
//  - DP kernel: ONE CTA, 512 threads, thread t owns columns 4t+1..4t+4 for
//    all rows, processes row i = s - t + 1 at step s (skewed systolic).
//    Strip-edge (last cell + scale K) crosses threads via a 3-slot rotating
//    SMEM float4 buffer; one __syncthreads per step; 2559 steps.
//    No cross-CTA protocol (R8-R12 showed inter-CTA pipelining serializes).

#define NN 2048
#define MM 2048
#define TT 512
#define C  4
#define STEPS (NN + TT - 1)

static_assert(TT * C == MM, "column coverage");

// 3 planes x NN*TT float4 = 48 MB scratch (fits in 126 MB L2).
__device__ float4 g_eth[3][(size_t)NN * TT];

__device__ __forceinline__ float exp2i(int n) {  // 2^n, clamped to normals
    n = max(-126, min(127, n));
    return __int_as_float((n + 127) << 23);
}

// exp(theta) precompute + relayout. One thread per (row i, dp-thread t).
// theta is row-major [i][j][s]; the 12 floats for (i, cols 4t..4t+3) are the
// 3 consecutive float4s at float4-index i*1536 + 3t.
__global__ void eth_kernel(const float* __restrict__ theta) {
    const float4* t4 = reinterpret_cast<const float4*>(theta);
    const size_t k = (size_t)blockIdx.x * blockDim.x + threadIdx.x;
    if (k >= (size_t)NN * TT) return;
    const size_t src = (k >> 9) * 1536 + (k & 511) * 3;
#pragma unroll
    for (int q = 0; q < 3; ++q) {
        float4 v = t4[src + q];
        g_eth[q][k] = make_float4(__expf(v.x), __expf(v.y),
                                  __expf(v.z), __expf(v.w));
    }
}

__global__ __launch_bounds__(TT, 1)
void ViterbiDecoder_5506148073875_kernel(const float* __restrict__ A,
                                         float* __restrict__ out) {
    // Edge buffer: (em, ex, ey, K-as-float-bits) of each thread's LAST cell.
    // Step s writes slot s%3; step s reads slot (s-1)%3 (row i of t-1) and
    // slot (s-2)%3 (row i-1 of t-1).
    __shared__ float4 edge[3][TT];

    const int t = threadIdx.x;

    const float ea00 = __expf(A[0]), ea01 = __expf(A[1]), ea02 = __expf(A[2]);
    const float ea10 = __expf(A[3]), ea11 = __expf(A[4]), ea12 = __expf(A[5]);
    const float ea20 = __expf(A[6]), ea21 = __expf(A[7]), ea22 = __expf(A[8]);

    // Previous-row state for 4 cells: p[c*3 + {m,x,y}], common scale K.
    float p[12];
#pragma unroll
    for (int k = 0; k < 12; ++k) p[k] = 0.f;  // row 0: V=-inf -> 0
    int K = 0;

    // Zeros in all slots = row-0 / not-yet-written semantics (V=-inf -> 0).
#pragma unroll
    for (int sl = 0; sl < 3; ++sl) edge[sl][t] = make_float4(0.f, 0.f, 0.f, 0.f);

    // Preload exp(theta) for this thread's first row (i = 1): index (1-1)*TT+t.
    float4 e0 = g_eth[0][t], e1 = g_eth[1][t], e2 = g_eth[2][t];
    __syncthreads();

    for (int s = 0; s < STEPS; ++s) {
        const int i = s - t + 1;  // 1-based row this thread computes

        if (i >= 1 && i <= NN) {
            // Neighbor column 4t (1-based): left = row i, diag = row i-1.
            float lm, lx, ly, dm, dx, dy; int lk, dk;
            if (t == 0) {
                lm = 0.f; lx = 0.f; ly = 0.f; lk = 0;          // V[i,0] = -inf
                dm = (i == 1) ? 1.f : 0.f; dx = 0.f; dy = 0.f; // V[0,0]=(1,0,0)
                dk = 0;
            } else {
                const float4 eL = edge[(s + 2) % 3][t - 1];    // (s-1)%3
                const float4 eD = edge[(s + 1) % 3][t - 1];    // (s-2)%3
                lm = eL.x; lx = eL.y; ly = eL.z; lk = __float_as_int(eL.w);
                dm = eD.x; dx = eD.y; dy = eD.z; dk = __float_as_int(eD.w);
            }

            // Align own / left / diag to the largest scale.
            const int kref = max(K, max(lk, dk));
            const float fo = exp2i(K  - kref);
            const float fl = exp2i(lk - kref);
            const float fd = exp2i(dk - kref);

            float sp[12];
#pragma unroll
            for (int k = 0; k < 12; ++k) sp[k] = p[k] * fo;

            const float bdm = dm * fd, bdx = dx * fd, bdy = dy * fd;
            const float blm = lm * fl, blx = lx * fl, bly = ly * fl;

            const float th[12] = {e0.x, e0.y, e0.z, e0.w,
                                  e1.x, e1.y, e1.z, e1.w,
                                  e2.x, e2.y, e2.z, e2.w};

            float n[12];
#pragma unroll
            for (int c = 0; c < 4; ++c) {
                const float cdm = (c == 0) ? bdm : sp[3*c - 3];
                const float cdx = (c == 0) ? bdx : sp[3*c - 2];
                const float cdy = (c == 0) ? bdy : sp[3*c - 1];
                const float clm = (c == 0) ? blm : n[3*c - 3];
                const float clx = (c == 0) ? blx : n[3*c - 2];
                const float cly = (c == 0) ? bly : n[3*c - 1];
                n[3*c + 0] = th[3*c + 0] *
                    fmaf(cdm, ea00, fmaf(cdx, ea01, cdy * ea02));
                n[3*c + 1] = th[3*c + 1] *
                    fmaf(sp[3*c], ea10, fmaf(sp[3*c+1], ea11, sp[3*c+2] * ea12));
                n[3*c + 2] = th[3*c + 2] *
                    fmaf(clm, ea20, fmaf(clx, ea21, cly * ea22));
            }

            // Renormalize so the row max lands in [1,2); bump scale K.
            float mx = n[0];
#pragma unroll
            for (int k = 1; k < 12; ++k) mx = fmaxf(mx, n[k]);
            const int   sh = ((__float_as_int(mx) >> 23) & 0xff) - 127;
            const float fn = exp2i(-sh);
#pragma unroll
            for (int k = 0; k < 12; ++k) p[k] = n[k] * fn;
            K = kref + sh;

            // Publish last cell for thread t+1.
            edge[s % 3][t] = make_float4(p[9], p[10], p[11], __int_as_float(K));

            if (t == TT - 1 && i == NN)
                out[0] = (float)K * 0.69314718055994531f +
                         logf(p[9] + p[10] + p[11]);
        }

        // Prefetch exp(theta) for next row (L2-resident after first replay;
        // latency covered by the barrier + next step's FFMA phase).
        const int inext = i + 1;
        if (inext >= 1 && inext <= NN) {
            const size_t b = (size_t)(inext - 1) * TT + t;
            e0 = g_eth[0][b]; e1 = g_eth[1][b]; e2 = g_eth[2][b];
        }
        __syncthreads();
    }
}

extern "C" void kernel_launch(void* const* d_in, const int* in_sizes, int n_in,
                              void* d_out, int out_size) {
    const float* theta = (const float*)d_in[0];
    const float* A     = (const float*)d_in[1];
    if (n_in >= 2 && in_sizes[0] == 9) {  // defensive: swap if order differs
        theta = (const float*)d_in[1];
        A     = (const float*)d_in[0];
    }
    eth_kernel<<<(NN * TT) / 256, 256>>>(theta);  // exp(theta) + relayout
    ViterbiDecoder_5506148073875_kernel<<<1, TT>>>(A, (float*)d_out);
}